// round 1
// baseline (speedup 1.0000x reference)
#include <cuda_runtime.h>

#define NUSERS  100000
#define NITEMS  50000
#define NNODES  150000
#define DIM     64
#define DIM4    16              // DIM/4 float4s per row
#define NEDGES  2400000

// Scratch (allocation-free: __device__ globals)
__device__ float g_bufA[NNODES * DIM];
__device__ float g_bufB[NNODES * DIM];
__device__ float g_deg[NNODES];          // degree -> rnorm (in place)
__device__ float g_enorm[NEDGES];        // per-edge norm

// ---------------------------------------------------------------------------
// init: bufA = x0 = concat(user_emb, item_emb); bufB = 0; out = 0.25*x0
// ---------------------------------------------------------------------------
__global__ void k_init(const float4* __restrict__ ue, const float4* __restrict__ ie,
                       float4* __restrict__ out) {
    int i = blockIdx.x * blockDim.x + threadIdx.x;
    const int n4 = NNODES * DIM4;
    if (i >= n4) return;
    const int u4 = NUSERS * DIM4;
    float4 v = (i < u4) ? ue[i] : ie[i - u4];
    ((float4*)g_bufA)[i] = v;
    ((float4*)g_bufB)[i] = make_float4(0.f, 0.f, 0.f, 0.f);
    out[i] = make_float4(0.25f * v.x, 0.25f * v.y, 0.25f * v.z, 0.25f * v.w);
}

__global__ void k_zerodeg() {
    int i = blockIdx.x * blockDim.x + threadIdx.x;
    if (i < NNODES) g_deg[i] = 0.f;
}

// degree = bincount(row); counts < 2^24 so f32 atomic adds are exact.
__global__ void k_deg(const int* __restrict__ row) {
    int e = blockIdx.x * blockDim.x + threadIdx.x;
    if (e < NEDGES) atomicAdd(&g_deg[row[e]], 1.0f);
}

__global__ void k_rnorm() {
    int i = blockIdx.x * blockDim.x + threadIdx.x;
    if (i < NNODES) g_deg[i] = rsqrtf(fmaxf(g_deg[i], 1.0f));
}

__global__ void k_enorm(const int* __restrict__ row, const int* __restrict__ col) {
    int e = blockIdx.x * blockDim.x + threadIdx.x;
    if (e < NEDGES) g_enorm[e] = g_deg[row[e]] * g_deg[col[e]];
}

// ---------------------------------------------------------------------------
// Scatter layer: 16 threads per edge, each handles a float4 of the 64-wide row.
// dst[row] += src[col] * norm[e] via vectorized L2 reduction (no return trip).
// ---------------------------------------------------------------------------
__global__ void k_scatter(const int* __restrict__ row, const int* __restrict__ col,
                          const float4* __restrict__ src, float* __restrict__ dst) {
    int t = blockIdx.x * blockDim.x + threadIdx.x;
    int e = t >> 4;
    int l = t & 15;
    if (e >= NEDGES) return;
    int r = __ldg(row + e);
    int c = __ldg(col + e);
    float nrm = __ldg(g_enorm + e);
    float4 v = src[c * DIM4 + l];
    float* p = dst + r * DIM + l * 4;
    asm volatile("red.global.add.v4.f32 [%0], {%1, %2, %3, %4};"
                 :: "l"(p), "f"(v.x * nrm), "f"(v.y * nrm), "f"(v.z * nrm), "f"(v.w * nrm)
                 : "memory");
}

// ---------------------------------------------------------------------------
// accum: out += 0.25 * xn;  optionally zero the buffer reused as next target
// ---------------------------------------------------------------------------
__global__ void k_accum(float4* __restrict__ out, const float4* __restrict__ xn,
                        float4* __restrict__ tozero) {
    int i = blockIdx.x * blockDim.x + threadIdx.x;
    const int n4 = NNODES * DIM4;
    if (i >= n4) return;
    float4 x = xn[i];
    float4 o = out[i];
    o.x += 0.25f * x.x;
    o.y += 0.25f * x.y;
    o.z += 0.25f * x.z;
    o.w += 0.25f * x.w;
    out[i] = o;
    if (tozero) tozero[i] = make_float4(0.f, 0.f, 0.f, 0.f);
}

extern "C" void kernel_launch(void* const* d_in, const int* in_sizes, int n_in,
                              void* d_out, int out_size) {
    const float* ue = (const float*)d_in[0];
    const float* ie = (const float*)d_in[1];
    const int*   ei = (const int*)d_in[2];
    const int* row = ei;              // edge_index[0, :]
    const int* col = ei + NEDGES;     // edge_index[1, :]
    float* out = (float*)d_out;

    float *bufA = nullptr, *bufB = nullptr;
    cudaGetSymbolAddress((void**)&bufA, g_bufA);
    cudaGetSymbolAddress((void**)&bufB, g_bufB);

    const int n4 = NNODES * DIM4;
    const int TPB = 256;
    dim3 gElem((n4 + TPB - 1) / TPB);
    dim3 gNode((NNODES + TPB - 1) / TPB);
    dim3 gEdge((NEDGES + TPB - 1) / TPB);
    dim3 gScat(((long long)NEDGES * 16 + TPB - 1) / TPB);

    k_init<<<gElem, TPB>>>((const float4*)ue, (const float4*)ie, (float4*)out);
    k_zerodeg<<<gNode, TPB>>>();
    k_deg<<<gEdge, TPB>>>(row);
    k_rnorm<<<gNode, TPB>>>();
    k_enorm<<<gEdge, TPB>>>(row, col);

    // Layer 1: x1 = P(x0) : read A -> write B; then out += 0.25*B, zero A
    k_scatter<<<gScat, TPB>>>(row, col, (const float4*)bufA, bufB);
    k_accum<<<gElem, TPB>>>((float4*)out, (const float4*)bufB, (float4*)bufA);
    // Layer 2: x2 = P(x1) : read B -> write A; then out += 0.25*A, zero B
    k_scatter<<<gScat, TPB>>>(row, col, (const float4*)bufB, bufA);
    k_accum<<<gElem, TPB>>>((float4*)out, (const float4*)bufA, (float4*)bufB);
    // Layer 3: x3 = P(x2) : read A -> write B; then out += 0.25*B
    k_scatter<<<gScat, TPB>>>(row, col, (const float4*)bufA, bufB);
    k_accum<<<gElem, TPB>>>((float4*)out, (const float4*)bufB, nullptr);
}

// round 2
// speedup vs baseline: 2.2136x; 2.2136x over previous
#include <cuda_runtime.h>

#define NUSERS  100000
#define NITEMS  50000
#define NNODES  150000
#define DIM     64
#define DIM4    16
#define NEDGES  2400000
#define SCAN_TPB 256
#define NBLK    ((NNODES + SCAN_TPB - 1) / SCAN_TPB)   // 586

// ---------------- allocation-free scratch ----------------
__device__ float g_bufA[NNODES * DIM];     // 38.4 MB
__device__ float g_bufB[NNODES * DIM];     // 38.4 MB
__device__ uint2 g_pair[NEDGES];           // 19.2 MB (col, norm-bits) sorted by row
__device__ int   g_deg[NNODES];
__device__ int   g_off[NNODES + 1];
__device__ int   g_cursor[NNODES];
__device__ float g_rnorm[NNODES];
__device__ int   g_partial[NBLK];

// ---------------- preprocessing ----------------
__global__ void k_zero() {
    int i = blockIdx.x * blockDim.x + threadIdx.x;
    if (i < NNODES) g_deg[i] = 0;
}

__global__ void k_deg(const int* __restrict__ row) {
    int e = blockIdx.x * blockDim.x + threadIdx.x;
    if (e < NEDGES) atomicAdd(&g_deg[row[e]], 1);
}

// block-local exclusive scan of degrees -> g_off (local), block totals -> g_partial
__global__ void k_scan1() {
    __shared__ int sh[SCAN_TPB];
    int i = blockIdx.x * SCAN_TPB + threadIdx.x;
    int v = (i < NNODES) ? g_deg[i] : 0;
    sh[threadIdx.x] = v;
    __syncthreads();
    for (int off = 1; off < SCAN_TPB; off <<= 1) {
        int t = (threadIdx.x >= off) ? sh[threadIdx.x - off] : 0;
        __syncthreads();
        sh[threadIdx.x] += t;
        __syncthreads();
    }
    if (i < NNODES) g_off[i] = sh[threadIdx.x] - v;   // exclusive
    if (threadIdx.x == SCAN_TPB - 1) g_partial[blockIdx.x] = sh[SCAN_TPB - 1];
}

// single-block exclusive scan of the 586 block totals
__global__ void k_scan2() {
    __shared__ int sh[1024];
    int t = threadIdx.x;
    int v = (t < NBLK) ? g_partial[t] : 0;
    sh[t] = v;
    __syncthreads();
    for (int off = 1; off < 1024; off <<= 1) {
        int u = (t >= off) ? sh[t - off] : 0;
        __syncthreads();
        sh[t] += u;
        __syncthreads();
    }
    if (t < NBLK) g_partial[t] = sh[t] - v;           // exclusive
}

// finalize offsets + cursors + rnorm
__global__ void k_scan3() {
    int i = blockIdx.x * blockDim.x + threadIdx.x;
    if (i < NNODES) {
        int off = g_off[i] + g_partial[i / SCAN_TPB];
        g_off[i] = off;
        g_cursor[i] = off;
        g_rnorm[i] = rsqrtf(fmaxf((float)g_deg[i], 1.0f));
    }
    if (i == 0) g_off[NNODES] = NEDGES;
}

// bucket edges by destination row; store (col, norm) as one 8B pair
__global__ void k_bucket(const int* __restrict__ row, const int* __restrict__ col) {
    int e = blockIdx.x * blockDim.x + threadIdx.x;
    if (e >= NEDGES) return;
    int r = row[e];
    int c = col[e];
    float nrm = g_rnorm[r] * g_rnorm[c];
    int pos = atomicAdd(&g_cursor[r], 1);
    g_pair[pos] = make_uint2((unsigned)c, __float_as_uint(nrm));
}

// ---------------- propagation layers (pull, no atomics) ----------------
// 16 threads per node, lane l owns float4 chunk l of the 64-wide row.

__global__ void k_layer1(const float4* __restrict__ ue, const float4* __restrict__ ie,
                         float4* __restrict__ dst, float4* __restrict__ out) {
    int g = blockIdx.x * blockDim.x + threadIdx.x;
    int node = g >> 4, l = g & 15;
    if (node >= NNODES) return;
    int s = g_off[node], e = g_off[node + 1];
    float4 acc = make_float4(0.f, 0.f, 0.f, 0.f);
    for (int k = s; k < e; k++) {
        uint2 p = g_pair[k];                       // broadcast within group
        int c = (int)p.x;
        float nrm = __uint_as_float(p.y);
        const float4* base = (c < NUSERS) ? (ue + (size_t)c * DIM4)
                                          : (ie + (size_t)(c - NUSERS) * DIM4);
        float4 v = __ldg(base + l);
        acc.x += v.x * nrm; acc.y += v.y * nrm;
        acc.z += v.z * nrm; acc.w += v.w * nrm;
    }
    // own x0 row for the out seed
    const float4* self = (node < NUSERS) ? (ue + (size_t)node * DIM4)
                                         : (ie + (size_t)(node - NUSERS) * DIM4);
    float4 x0 = __ldg(self + l);
    size_t idx = (size_t)node * DIM4 + l;
    dst[idx] = acc;
    out[idx] = make_float4(0.25f * (x0.x + acc.x), 0.25f * (x0.y + acc.y),
                           0.25f * (x0.z + acc.z), 0.25f * (x0.w + acc.w));
}

// generic layer: read src, optionally write dst, out += 0.25*acc
template <bool WRITE_DST>
__global__ void k_layerN(const float4* __restrict__ src,
                         float4* __restrict__ dst, float4* __restrict__ out) {
    int g = blockIdx.x * blockDim.x + threadIdx.x;
    int node = g >> 4, l = g & 15;
    if (node >= NNODES) return;
    int s = g_off[node], e = g_off[node + 1];
    float4 acc = make_float4(0.f, 0.f, 0.f, 0.f);
    for (int k = s; k < e; k++) {
        uint2 p = g_pair[k];
        int c = (int)p.x;
        float nrm = __uint_as_float(p.y);
        float4 v = __ldg(src + (size_t)c * DIM4 + l);
        acc.x += v.x * nrm; acc.y += v.y * nrm;
        acc.z += v.z * nrm; acc.w += v.w * nrm;
    }
    size_t idx = (size_t)node * DIM4 + l;
    if (WRITE_DST) dst[idx] = acc;
    float4 o = out[idx];
    o.x += 0.25f * acc.x; o.y += 0.25f * acc.y;
    o.z += 0.25f * acc.z; o.w += 0.25f * acc.w;
    out[idx] = o;
}

extern "C" void kernel_launch(void* const* d_in, const int* in_sizes, int n_in,
                              void* d_out, int out_size) {
    const float* ue = (const float*)d_in[0];
    const float* ie = (const float*)d_in[1];
    const int*   ei = (const int*)d_in[2];
    const int* row = ei;
    const int* col = ei + NEDGES;
    float* out = (float*)d_out;

    float *bufA = nullptr, *bufB = nullptr;
    cudaGetSymbolAddress((void**)&bufA, g_bufA);
    cudaGetSymbolAddress((void**)&bufB, g_bufB);

    const int TPB = 256;
    dim3 gNode((NNODES + TPB - 1) / TPB);
    dim3 gEdge((NEDGES + TPB - 1) / TPB);
    dim3 gLayer(((long long)NNODES * 16 + TPB - 1) / TPB);

    // preprocessing: degree -> scan -> bucket
    k_zero<<<gNode, TPB>>>();
    k_deg<<<gEdge, TPB>>>(row);
    k_scan1<<<NBLK, SCAN_TPB>>>();
    k_scan2<<<1, 1024>>>();
    k_scan3<<<gNode, TPB>>>();
    k_bucket<<<gEdge, TPB>>>(row, col);

    // layer 1: x1 = P(x0) from embedding tables; out = 0.25*(x0+x1); x1 -> bufB
    k_layer1<<<gLayer, TPB>>>((const float4*)ue, (const float4*)ie,
                              (float4*)bufB, (float4*)out);
    // layer 2: x2 = P(x1); out += 0.25*x2; x2 -> bufA
    k_layerN<true><<<gLayer, TPB>>>((const float4*)bufB, (float4*)bufA, (float4*)out);
    // layer 3: x3 = P(x2); out += 0.25*x3 (no buffer write)
    k_layerN<false><<<gLayer, TPB>>>((const float4*)bufA, nullptr, (float4*)out);
}

// round 3
// speedup vs baseline: 2.7893x; 1.2600x over previous
#include <cuda_runtime.h>
#include <cuda_fp16.h>

#define NUSERS  100000
#define NITEMS  50000
#define NNODES  150000
#define DIM     64
#define NEDGES  2400000
#define SCAN_TPB 256
#define NBLK    ((NNODES + SCAN_TPB - 1) / SCAN_TPB)   // 586

// ---------------- allocation-free scratch ----------------
__device__ uint4 g_h0[NNODES * 8];      // fp16 x0   (19.2 MB)
__device__ uint4 g_h1[NNODES * 8];      // fp16 x1
__device__ uint4 g_h2[NNODES * 8];      // fp16 x2
__device__ uint2 g_pair[NEDGES];        // (col*8, norm-bits) bucketed by row
__device__ int   g_deg[NNODES];
__device__ int   g_off[NNODES + 1];
__device__ int   g_cursor[NNODES];
__device__ float g_rnorm[NNODES];
__device__ int   g_partial[NBLK];

// ---------------- preprocessing ----------------
__global__ void k_deg(const int* __restrict__ row) {
    int e = blockIdx.x * blockDim.x + threadIdx.x;
    if (e < NEDGES) atomicAdd(&g_deg[row[e]], 1);
}

__global__ void k_scan1() {
    __shared__ int sh[SCAN_TPB];
    int i = blockIdx.x * SCAN_TPB + threadIdx.x;
    int v = (i < NNODES) ? g_deg[i] : 0;
    sh[threadIdx.x] = v;
    __syncthreads();
    for (int off = 1; off < SCAN_TPB; off <<= 1) {
        int t = (threadIdx.x >= off) ? sh[threadIdx.x - off] : 0;
        __syncthreads();
        sh[threadIdx.x] += t;
        __syncthreads();
    }
    if (i < NNODES) g_off[i] = sh[threadIdx.x] - v;   // block-local exclusive
    if (threadIdx.x == SCAN_TPB - 1) g_partial[blockIdx.x] = sh[SCAN_TPB - 1];
}

// shuffle-based exclusive scan of the 586 block totals (1 block, 1024 thr)
__global__ void k_scan2() {
    __shared__ int warpsum[32];
    int t = threadIdx.x;
    int lane = t & 31, warp = t >> 5;
    int v = (t < NBLK) ? g_partial[t] : 0;
    int x = v;
    #pragma unroll
    for (int o = 1; o < 32; o <<= 1) {
        int y = __shfl_up_sync(0xffffffffu, x, o);
        if (lane >= o) x += y;
    }
    if (lane == 31) warpsum[warp] = x;
    __syncthreads();
    if (warp == 0) {
        int w = warpsum[lane];
        #pragma unroll
        for (int o = 1; o < 32; o <<= 1) {
            int y = __shfl_up_sync(0xffffffffu, w, o);
            if (lane >= o) w += y;
        }
        warpsum[lane] = w - warpsum[lane];   // exclusive warp offsets
    }
    __syncthreads();
    if (t < NBLK) g_partial[t] = x - v + warpsum[warp];
}

__global__ void k_scan3() {
    int i = blockIdx.x * blockDim.x + threadIdx.x;
    if (i < NNODES) {
        int off = g_off[i] + g_partial[i / SCAN_TPB];
        g_off[i] = off;
        g_cursor[i] = off;
        g_rnorm[i] = rsqrtf(fmaxf((float)g_deg[i], 1.0f));
    }
    if (i == 0) g_off[NNODES] = NEDGES;
}

__global__ void k_bucket(const int* __restrict__ row, const int* __restrict__ col) {
    int e = blockIdx.x * blockDim.x + threadIdx.x;
    if (e >= NEDGES) return;
    int r = row[e];
    int c = col[e];
    float nrm = g_rnorm[r] * g_rnorm[c];
    int pos = atomicAdd(&g_cursor[r], 1);
    g_pair[pos] = make_uint2((unsigned)(c << 3), __float_as_uint(nrm));
}

// fp32 tables -> fp16 cache
__global__ void k_tohalf(const float2* __restrict__ ue, const float2* __restrict__ ie) {
    int i = blockIdx.x * blockDim.x + threadIdx.x;   // half2 index
    const int n2 = NNODES * 32;
    if (i >= n2) return;
    const int u2 = NUSERS * 32;
    float2 v = (i < u2) ? ue[i] : ie[i - u2];
    ((__half2*)g_h0)[i] = __floats2half2_rn(v.x, v.y);
}

// ---------------- propagation: 8 threads/node, lane owns 8 halves (16B) ----
__device__ __forceinline__ void acc_uint4(const uint4& h, float nrm, float* a) {
    float2 f0 = __half22float2(*(const __half2*)&h.x);
    float2 f1 = __half22float2(*(const __half2*)&h.y);
    float2 f2 = __half22float2(*(const __half2*)&h.z);
    float2 f3 = __half22float2(*(const __half2*)&h.w);
    a[0] += f0.x * nrm; a[1] += f0.y * nrm;
    a[2] += f1.x * nrm; a[3] += f1.y * nrm;
    a[4] += f2.x * nrm; a[5] += f2.y * nrm;
    a[6] += f3.x * nrm; a[7] += f3.y * nrm;
}

__global__ void k_layer_mid(const uint4* __restrict__ hsrc, uint4* __restrict__ hdst) {
    int g = blockIdx.x * blockDim.x + threadIdx.x;
    int node = g >> 3, l = g & 7;
    if (node >= NNODES) return;
    int s = g_off[node], e = g_off[node + 1];
    float a[8] = {0.f, 0.f, 0.f, 0.f, 0.f, 0.f, 0.f, 0.f};
    #pragma unroll 4
    for (int k = s; k < e; k++) {
        uint2 p = __ldg(&g_pair[k]);
        uint4 h = __ldg(&hsrc[p.x + l]);
        acc_uint4(h, __uint_as_float(p.y), a);
    }
    uint4 o;
    *(__half2*)&o.x = __floats2half2_rn(a[0], a[1]);
    *(__half2*)&o.y = __floats2half2_rn(a[2], a[3]);
    *(__half2*)&o.z = __floats2half2_rn(a[4], a[5]);
    *(__half2*)&o.w = __floats2half2_rn(a[6], a[7]);
    hdst[node * 8 + l] = o;
}

// final layer: acc=x3; read x0 (fp32 tables), x1, x2 (fp16); write out once
__global__ void k_layer3(const uint4* __restrict__ hsrc,
                         const float4* __restrict__ ue, const float4* __restrict__ ie,
                         float4* __restrict__ out) {
    int g = blockIdx.x * blockDim.x + threadIdx.x;
    int node = g >> 3, l = g & 7;
    if (node >= NNODES) return;
    int s = g_off[node], e = g_off[node + 1];
    float a[8] = {0.f, 0.f, 0.f, 0.f, 0.f, 0.f, 0.f, 0.f};
    #pragma unroll 4
    for (int k = s; k < e; k++) {
        uint2 p = __ldg(&g_pair[k]);
        uint4 h = __ldg(&hsrc[p.x + l]);
        acc_uint4(h, __uint_as_float(p.y), a);
    }
    // add x1, x2 (own row, fp16)
    acc_uint4(__ldg(&g_h1[node * 8 + l]), 1.0f, a);
    acc_uint4(__ldg(&g_h2[node * 8 + l]), 1.0f, a);
    // add x0 from fp32 tables
    const float4* self = (node < NUSERS) ? (ue + (size_t)node * 16)
                                         : (ie + (size_t)(node - NUSERS) * 16);
    float4 x0a = __ldg(self + l * 2);
    float4 x0b = __ldg(self + l * 2 + 1);
    a[0] += x0a.x; a[1] += x0a.y; a[2] += x0a.z; a[3] += x0a.w;
    a[4] += x0b.x; a[5] += x0b.y; a[6] += x0b.z; a[7] += x0b.w;
    size_t idx = (size_t)node * 16 + l * 2;
    out[idx]     = make_float4(0.25f * a[0], 0.25f * a[1], 0.25f * a[2], 0.25f * a[3]);
    out[idx + 1] = make_float4(0.25f * a[4], 0.25f * a[5], 0.25f * a[6], 0.25f * a[7]);
}

extern "C" void kernel_launch(void* const* d_in, const int* in_sizes, int n_in,
                              void* d_out, int out_size) {
    const float* ue = (const float*)d_in[0];
    const float* ie = (const float*)d_in[1];
    const int*   ei = (const int*)d_in[2];
    const int* row = ei;
    const int* col = ei + NEDGES;
    float* out = (float*)d_out;

    void *h0, *h1, *h2, *degp;
    cudaGetSymbolAddress(&h0, g_h0);
    cudaGetSymbolAddress(&h1, g_h1);
    cudaGetSymbolAddress(&h2, g_h2);
    cudaGetSymbolAddress(&degp, g_deg);

    const int TPB = 256;
    dim3 gNode((NNODES + TPB - 1) / TPB);
    dim3 gEdge((NEDGES + TPB - 1) / TPB);
    dim3 gHalf((NNODES * 32 + TPB - 1) / TPB);
    dim3 gLayer((NNODES * 8 + TPB - 1) / TPB);

    cudaMemsetAsync(degp, 0, NNODES * sizeof(int));
    k_tohalf<<<gHalf, TPB>>>((const float2*)ue, (const float2*)ie);
    k_deg<<<gEdge, TPB>>>(row);
    k_scan1<<<NBLK, SCAN_TPB>>>();
    k_scan2<<<1, 1024>>>();
    k_scan3<<<gNode, TPB>>>();
    k_bucket<<<gEdge, TPB>>>(row, col);

    k_layer_mid<<<gLayer, TPB>>>((const uint4*)h0, (uint4*)h1);   // x1
    k_layer_mid<<<gLayer, TPB>>>((const uint4*)h1, (uint4*)h2);   // x2
    k_layer3<<<gLayer, TPB>>>((const uint4*)h2,
                              (const float4*)ue, (const float4*)ie, (float4*)out);
}